// round 1
// baseline (speedup 1.0000x reference)
#include <cuda_runtime.h>

// ---------------- device scratch (no runtime allocation allowed) ----------------
__device__ float  gS[32 * 64 * 9];     // strided sums for cond conv
__device__ float  gDw[32 * 576];       // per-sample depthwise weights
__device__ float  gPw[32 * 4096];      // per-sample pointwise weights [b][o][c]
__device__ float  gDb[32 * 64];        // per-sample dynamic bias
__device__ double gSum[64], gSumSq[64];// BN statistics accumulators
__device__ float  gScale[64], gShift[64];

// =================================================================================
// Kernel 0: zero stats (graph replays must be deterministic)
// =================================================================================
__global__ void k_zero() {
    int t = threadIdx.x;
    if (t < 64) { gSum[t] = 0.0; gSumSq[t] = 0.0; }
}

// =================================================================================
// Kernel 1: per-(b,c) 9 strided sums S[kh][kw] = sum_{oh,ow} x[2oh+kh, 2ow+kw]
//   valid output range oh,ow in [0,62]  (conv3x3 stride2 VALID on 128x128 -> 63x63)
// =================================================================================
__global__ void __launch_bounds__(256) k_cond_sums(const float* __restrict__ x) {
    int bc = blockIdx.x;                 // b*64 + c
    int t  = threadIdx.x;
    const float* base = x + (size_t)bc * 16384;

    int i  = t >> 1;                     // row 0..127
    int j0 = (t & 1) * 64;               // half-row
    const float4* row4 = (const float4*)(base + i * 128 + j0);

    // column-class partial sums (kw = 0,1,2)
    float ca0 = 0.f, ca1 = 0.f, ca2 = 0.f;
#pragma unroll
    for (int k = 0; k < 16; k++) {
        float4 v = row4[k];
        int j = j0 + 4 * k;              // even column of v.x
        // kw=0: even col <=124 ; kw=1: odd col <=125 ; kw=2: even col >=2
        ca0 += v.x + ((j <= 122) ? v.z : 0.f);
        ca1 += v.y + ((j <= 122) ? v.w : 0.f);
        ca2 += ((j >= 2) ? v.x : 0.f) + v.z;
    }
    bool ev = ((i & 1) == 0);
    float f0 = (ev  && i <= 124) ? 1.f : 0.f;   // kh=0: even row <=124
    float f1 = (!ev && i <= 125) ? 1.f : 0.f;   // kh=1: odd  row <=125
    float f2 = (ev  && i >= 2)   ? 1.f : 0.f;   // kh=2: even row >=2

    float bins[9] = { f0*ca0, f0*ca1, f0*ca2,
                      f1*ca0, f1*ca1, f1*ca2,
                      f2*ca0, f2*ca1, f2*ca2 };
#pragma unroll
    for (int off = 16; off; off >>= 1)
#pragma unroll
        for (int k = 0; k < 9; k++)
            bins[k] += __shfl_down_sync(0xffffffffu, bins[k], off);

    __shared__ float red[8][9];
    int lane = t & 31, w = t >> 5;
    if (lane == 0)
#pragma unroll
        for (int k = 0; k < 9; k++) red[w][k] = bins[k];
    __syncthreads();
    if (t < 9) {
        float s = 0.f;
#pragma unroll
        for (int ww = 0; ww < 8; ww++) s += red[ww][t];
        gS[bc * 9 + t] = s;
    }
}

// =================================================================================
// Kernel 2: per-sample condition vector + dynamic weight generation (tiny GEMMs)
// =================================================================================
__global__ void __launch_bounds__(256) k_gen(
    const float* __restrict__ cg_w1, const float* __restrict__ cg_b1,
    const float* __restrict__ cg_w2, const float* __restrict__ cg_b2,
    const float* __restrict__ wg_w,  const float* __restrict__ wg_b,
    const float* __restrict__ pg_w,  const float* __restrict__ pg_b,
    const float* __restrict__ bg_w,  const float* __restrict__ bg_b)
{
    __shared__ float Ss[576];
    __shared__ float parts[256];
    __shared__ float c0[16];
    __shared__ float cond[16];

    int b = blockIdx.x;
    int t = threadIdx.x;

    for (int idx = t; idx < 576; idx += 256) Ss[idx] = gS[b * 576 + idx];
    __syncthreads();

    // cond_pre[co] = (1/3969) * sum_{c,k} cg_w1[co,c,k] * S[c,k] + cg_b1
    {
        int co = t >> 4, part = t & 15;
        const float* wrow = cg_w1 + co * 576 + part * 36;
        const float* srow = Ss + part * 36;
        float s = 0.f;
#pragma unroll
        for (int k = 0; k < 36; k++) s += wrow[k] * srow[k];
        parts[t] = s;
    }
    __syncthreads();
    if (t < 16) {
        float s = 0.f;
#pragma unroll
        for (int p = 0; p < 16; p++) s += parts[t * 16 + p];
        s = s * (1.0f / 3969.0f) + cg_b1[t];
        c0[t] = fmaxf(s, 0.f);
    }
    __syncthreads();
    if (t < 16) {
        float s = cg_b2[t];
#pragma unroll
        for (int i = 0; i < 16; i++) s += c0[i] * cg_w2[t * 16 + i];
        cond[t] = fmaxf(s, 0.f);
    }
    __syncthreads();

    // depthwise weights: relu(cond @ wg_w.T + wg_b), 576 per sample
    for (int r = t; r < 576; r += 256) {
        float s = wg_b[r];
        const float* wr = wg_w + r * 16;
#pragma unroll
        for (int q = 0; q < 16; q++) s += cond[q] * wr[q];
        gDw[b * 576 + r] = fmaxf(s, 0.f);
    }
    // pointwise weights: relu(cond @ pg_w.T + pg_b), 4096 per sample; layout [o][c]
    for (int r = t; r < 4096; r += 256) {
        float s = pg_b[r];
        const float* wr = pg_w + r * 16;
#pragma unroll
        for (int q = 0; q < 16; q++) s += cond[q] * wr[q];
        gPw[b * 4096 + r] = fmaxf(s, 0.f);
    }
    // dynamic bias (no relu)
    if (t < 64) {
        float s = bg_b[t];
        const float* wr = bg_w + t * 16;
#pragma unroll
        for (int q = 0; q < 16; q++) s += cond[q] * wr[q];
        gDb[b * 64 + t] = s;
    }
}

// =================================================================================
// Kernel 3: fused depthwise3x3 + pointwise(64x64) + dbias + BN stat accumulation
//   one block per (h, b); 256 threads
// smem layout (floats):
//   xs  [3][64][136]   offset 0       (26112)  rows h-1,h,h+1; data at +4, zero pads at +3/+132
//   ys  [64][128]      offset 26112   (8192)
//   pw2 [64][64] f32x2 offset 34304   (8192)
//   dws [576]          offset 42496
//   dbs [64]           offset 43072     -> total 43136 floats = 172544 B
// =================================================================================
__global__ void __launch_bounds__(256, 1) k_main(const float* __restrict__ x,
                                                 float* __restrict__ out)
{
    extern __shared__ float sm[];
    float*  xs  = sm;
    float*  ys  = sm + 26112;
    float2* pw2 = (float2*)(sm + 34304);
    float*  dws = sm + 42496;
    float*  dbs = sm + 43072;

    int tid  = threadIdx.x;
    int lane = tid & 31, wid = tid >> 5;
    int h = blockIdx.x, b = blockIdx.y;

    // ---- load per-sample dynamic weights ----
    {
        const float* pwg = gPw + b * 4096;
#pragma unroll
        for (int k = 0; k < 16; k++) {
            int idx = tid + 256 * k;
            float v = pwg[idx];
            pw2[idx] = make_float2(v, v);
        }
        for (int idx = tid; idx < 576; idx += 256) dws[idx] = gDw[b * 576 + idx];
        if (tid < 64) dbs[tid] = gDb[b * 64 + tid];
    }
    // ---- load x halo rows (h-1, h, h+1) for all 64 channels ----
    {
        const float4* x4 = (const float4*)(x + (size_t)b * 64 * 16384);
        for (int q = tid; q < 6144; q += 256) {
            int r   = q >> 11;
            int rem = q & 2047;
            int c   = rem >> 5;
            int w4  = rem & 31;
            int hh  = h - 1 + r;
            float4 v = make_float4(0.f, 0.f, 0.f, 0.f);
            if ((unsigned)hh < 128u) v = x4[(c * 128 + hh) * 32 + w4];
            *(float4*)(xs + (r * 64 + c) * 136 + 4 + 4 * w4) = v;
        }
        for (int q = tid; q < 192; q += 256) {   // left/right zero pads
            int r = q >> 6, c = q & 63;
            xs[(r * 64 + c) * 136 + 3]   = 0.f;
            xs[(r * 64 + c) * 136 + 132] = 0.f;
        }
    }
    __syncthreads();

    // ---- depthwise 3x3, pad=1: warp w handles channels [8w, 8w+8) ----
#pragma unroll
    for (int ci = 0; ci < 8; ci++) {
        int c = wid * 8 + ci;
        const float* wp = dws + c * 9;
        float a0 = 0.f, a1 = 0.f, a2 = 0.f, a3 = 0.f;
#pragma unroll
        for (int r = 0; r < 3; r++) {
            const float* row = xs + (r * 64 + c) * 136 + 4;
            float4 m = *(const float4*)(row + 4 * lane);
            float lf = row[4 * lane - 1];
            float rg = row[4 * lane + 4];
            float w0 = wp[r * 3 + 0], w1 = wp[r * 3 + 1], w2 = wp[r * 3 + 2];
            a0 += w0 * lf  + w1 * m.x + w2 * m.y;
            a1 += w0 * m.x + w1 * m.y + w2 * m.z;
            a2 += w0 * m.y + w1 * m.z + w2 * m.w;
            a3 += w0 * m.z + w1 * m.w + w2 * rg;
        }
        *(float4*)(ys + c * 128 + 4 * lane) = make_float4(a0, a1, a2, a3);
    }
    __syncthreads();

    // ---- pointwise 64x64 with packed f32x2 FMA ----
    const unsigned long long* ys64 = (const unsigned long long*)ys;
    const unsigned long long* pw64 = (const unsigned long long*)pw2;
    unsigned long long acc[16];
#pragma unroll
    for (int i = 0; i < 16; i++) acc[i] = 0ull;
    int ob = wid * 8;

#pragma unroll 2
    for (int c = 0; c < 64; c++) {
        unsigned long long y0 = ys64[c * 64 + lane];        // w = 2l, 2l+1
        unsigned long long y1 = ys64[c * 64 + 32 + lane];   // w = 64+2l, 64+2l+1
#pragma unroll
        for (int oi = 0; oi < 8; oi++) {
            unsigned long long p = pw64[(ob + oi) * 64 + c];
            asm("fma.rn.f32x2 %0, %1, %2, %0;" : "+l"(acc[2 * oi])     : "l"(y0), "l"(p));
            asm("fma.rn.f32x2 %0, %1, %2, %0;" : "+l"(acc[2 * oi + 1]) : "l"(y1), "l"(p));
        }
    }

    // ---- epilogue: +dbias, store, BN partial stats ----
    float* outb = out + (size_t)(b * 64) * 16384 + (size_t)h * 128;
#pragma unroll
    for (int oi = 0; oi < 8; oi++) {
        int o = ob + oi;
        float db = dbs[o];
        float a0x, a0y, a1x, a1y;
        asm("mov.b64 {%0,%1}, %2;" : "=f"(a0x), "=f"(a0y) : "l"(acc[2 * oi]));
        asm("mov.b64 {%0,%1}, %2;" : "=f"(a1x), "=f"(a1y) : "l"(acc[2 * oi + 1]));
        a0x += db; a0y += db; a1x += db; a1y += db;

        float* orow = outb + (size_t)o * 16384;
        *(float2*)(orow + 2 * lane)      = make_float2(a0x, a0y);
        *(float2*)(orow + 64 + 2 * lane) = make_float2(a1x, a1y);

        float s  = (a0x + a0y) + (a1x + a1y);
        float s2 = a0x * a0x + a0y * a0y + a1x * a1x + a1y * a1y;
#pragma unroll
        for (int off = 16; off; off >>= 1) {
            s  += __shfl_down_sync(0xffffffffu, s,  off);
            s2 += __shfl_down_sync(0xffffffffu, s2, off);
        }
        if (lane == 0) {
            atomicAdd(&gSum[o],   (double)s);
            atomicAdd(&gSumSq[o], (double)s2);
        }
    }
}

// =================================================================================
// Kernel 4: finalize BN scale/shift
// =================================================================================
__global__ void k_finalize(const float* __restrict__ gamma,
                           const float* __restrict__ beta)
{
    int t = threadIdx.x;
    if (t < 64) {
        const double n = 524288.0;   // 32 * 128 * 128
        double mean = gSum[t] / n;
        double var  = gSumSq[t] / n - mean * mean;
        double inv  = 1.0 / sqrt(var + 1e-5);
        double g    = (double)gamma[t];
        gScale[t] = (float)(g * inv);
        gShift[t] = (float)((double)beta[t] - mean * g * inv);
    }
}

// =================================================================================
// Kernel 5: apply BN in place (streaming, float4)
// =================================================================================
__global__ void __launch_bounds__(256) k_bn(float* __restrict__ out) {
    int i = blockIdx.x * 256 + threadIdx.x;      // float4 index
    float4 v = ((const float4*)out)[i];
    int o = (i >> 12) & 63;                      // 4096 float4 per (b,o) plane
    float sc = gScale[o], sh = gShift[o];
    v.x = fmaf(v.x, sc, sh);
    v.y = fmaf(v.y, sc, sh);
    v.z = fmaf(v.z, sc, sh);
    v.w = fmaf(v.w, sc, sh);
    ((float4*)out)[i] = v;
}

// =================================================================================
extern "C" void kernel_launch(void* const* d_in, const int* in_sizes, int n_in,
                              void* d_out, int out_size)
{
    const float* x      = (const float*)d_in[0];
    const float* cg_w1  = (const float*)d_in[1];
    const float* cg_b1  = (const float*)d_in[2];
    const float* cg_w2  = (const float*)d_in[3];
    const float* cg_b2  = (const float*)d_in[4];
    const float* wg_w   = (const float*)d_in[5];
    const float* wg_b   = (const float*)d_in[6];
    const float* pg_w   = (const float*)d_in[7];
    const float* pg_b   = (const float*)d_in[8];
    const float* bg_w   = (const float*)d_in[9];
    const float* bg_b   = (const float*)d_in[10];
    const float* bn_g   = (const float*)d_in[11];
    const float* bn_b   = (const float*)d_in[12];
    float* out = (float*)d_out;

    cudaFuncSetAttribute(k_main, cudaFuncAttributeMaxDynamicSharedMemorySize, 172544);

    k_zero<<<1, 64>>>();
    k_cond_sums<<<2048, 256>>>(x);
    k_gen<<<32, 256>>>(cg_w1, cg_b1, cg_w2, cg_b2, wg_w, wg_b, pg_w, pg_b, bg_w, bg_b);
    dim3 g3(128, 32);
    k_main<<<g3, 256, 172544>>>(x, out);
    k_finalize<<<1, 64>>>(bn_g, bn_b);
    k_bn<<<32768, 256>>>(out);
}

// round 2
// speedup vs baseline: 1.3469x; 1.3469x over previous
#include <cuda_runtime.h>

// ---------------- device scratch (no runtime allocation allowed) ----------------
__device__ float  gS[32 * 64 * 9];     // strided sums for cond conv
__device__ float  gDw[32 * 576];       // per-sample depthwise weights
__device__ float  gPw[32 * 4096];      // per-sample pointwise weights [b][o][c]
__device__ float  gDb[32 * 64];        // per-sample dynamic bias
__device__ double gSum[64], gSumSq[64];// BN statistics accumulators
__device__ float  gScale[64], gShift[64];

// =================================================================================
// Kernel 0: zero stats (graph replays must be deterministic)
// =================================================================================
__global__ void k_zero() {
    int t = threadIdx.x;
    if (t < 64) { gSum[t] = 0.0; gSumSq[t] = 0.0; }
}

// =================================================================================
// Kernel 1: per-(b,c) 9 strided sums S[kh][kw] = sum_{oh,ow} x[2oh+kh, 2ow+kw]
// =================================================================================
__global__ void __launch_bounds__(256) k_cond_sums(const float* __restrict__ x) {
    int bc = blockIdx.x;                 // b*64 + c
    int t  = threadIdx.x;
    const float* base = x + (size_t)bc * 16384;

    int i  = t >> 1;                     // row 0..127
    int j0 = (t & 1) * 64;               // half-row
    const float4* row4 = (const float4*)(base + i * 128 + j0);

    float ca0 = 0.f, ca1 = 0.f, ca2 = 0.f;
#pragma unroll
    for (int k = 0; k < 16; k++) {
        float4 v = row4[k];
        int j = j0 + 4 * k;
        ca0 += v.x + ((j <= 122) ? v.z : 0.f);
        ca1 += v.y + ((j <= 122) ? v.w : 0.f);
        ca2 += ((j >= 2) ? v.x : 0.f) + v.z;
    }
    bool ev = ((i & 1) == 0);
    float f0 = (ev  && i <= 124) ? 1.f : 0.f;
    float f1 = (!ev && i <= 125) ? 1.f : 0.f;
    float f2 = (ev  && i >= 2)   ? 1.f : 0.f;

    float bins[9] = { f0*ca0, f0*ca1, f0*ca2,
                      f1*ca0, f1*ca1, f1*ca2,
                      f2*ca0, f2*ca1, f2*ca2 };
#pragma unroll
    for (int off = 16; off; off >>= 1)
#pragma unroll
        for (int k = 0; k < 9; k++)
            bins[k] += __shfl_down_sync(0xffffffffu, bins[k], off);

    __shared__ float red[8][9];
    int lane = t & 31, w = t >> 5;
    if (lane == 0)
#pragma unroll
        for (int k = 0; k < 9; k++) red[w][k] = bins[k];
    __syncthreads();
    if (t < 9) {
        float s = 0.f;
#pragma unroll
        for (int ww = 0; ww < 8; ww++) s += red[ww][t];
        gS[bc * 9 + t] = s;
    }
}

// =================================================================================
// Kernel 2: per-sample condition vector + dynamic weight generation (tiny GEMMs)
// =================================================================================
__global__ void __launch_bounds__(256) k_gen(
    const float* __restrict__ cg_w1, const float* __restrict__ cg_b1,
    const float* __restrict__ cg_w2, const float* __restrict__ cg_b2,
    const float* __restrict__ wg_w,  const float* __restrict__ wg_b,
    const float* __restrict__ pg_w,  const float* __restrict__ pg_b,
    const float* __restrict__ bg_w,  const float* __restrict__ bg_b)
{
    __shared__ float Ss[576];
    __shared__ float parts[256];
    __shared__ float c0[16];
    __shared__ float cond[16];

    int b = blockIdx.x;
    int t = threadIdx.x;

    for (int idx = t; idx < 576; idx += 256) Ss[idx] = gS[b * 576 + idx];
    __syncthreads();

    {
        int co = t >> 4, part = t & 15;
        const float* wrow = cg_w1 + co * 576 + part * 36;
        const float* srow = Ss + part * 36;
        float s = 0.f;
#pragma unroll
        for (int k = 0; k < 36; k++) s += wrow[k] * srow[k];
        parts[t] = s;
    }
    __syncthreads();
    if (t < 16) {
        float s = 0.f;
#pragma unroll
        for (int p = 0; p < 16; p++) s += parts[t * 16 + p];
        s = s * (1.0f / 3969.0f) + cg_b1[t];
        c0[t] = fmaxf(s, 0.f);
    }
    __syncthreads();
    if (t < 16) {
        float s = cg_b2[t];
#pragma unroll
        for (int i = 0; i < 16; i++) s += c0[i] * cg_w2[t * 16 + i];
        cond[t] = fmaxf(s, 0.f);
    }
    __syncthreads();

    for (int r = t; r < 576; r += 256) {
        float s = wg_b[r];
        const float* wr = wg_w + r * 16;
#pragma unroll
        for (int q = 0; q < 16; q++) s += cond[q] * wr[q];
        gDw[b * 576 + r] = fmaxf(s, 0.f);
    }
    for (int r = t; r < 4096; r += 256) {
        float s = pg_b[r];
        const float* wr = pg_w + r * 16;
#pragma unroll
        for (int q = 0; q < 16; q++) s += cond[q] * wr[q];
        gPw[b * 4096 + r] = fmaxf(s, 0.f);
    }
    if (t < 64) {
        float s = bg_b[t];
        const float* wr = bg_w + t * 16;
#pragma unroll
        for (int q = 0; q < 16; q++) s += cond[q] * wr[q];
        gDb[b * 64 + t] = s;
    }
}

// =================================================================================
// Kernel 3: fused depthwise3x3 (global->regs, shuffle halo) + pointwise(64x64)
//   + dbias + BN stat accumulation.  One block per (h, b); 256 threads.
// smem (floats):
//   ys  [64][128]      offset 0      (8192)
//   pw2 [64][64] f32x2 offset 8192   (8192)
//   dws [576]          offset 16384
//   dbs [64]           offset 16960   -> 17024 floats = 68096 B  -> 3 CTAs/SM
// =================================================================================
__global__ void __launch_bounds__(256, 3) k_main(const float* __restrict__ x,
                                                 float* __restrict__ out)
{
    extern __shared__ float sm[];
    float*  ys  = sm;
    float2* pw2 = (float2*)(sm + 8192);
    float*  dws = sm + 16384;
    float*  dbs = sm + 16960;

    int tid  = threadIdx.x;
    int lane = tid & 31, wid = tid >> 5;
    int h = blockIdx.x, b = blockIdx.y;

    // ---- stage per-sample dynamic weights into smem ----
    {
        const float* pwg = gPw + b * 4096;
#pragma unroll
        for (int k = 0; k < 16; k++) {
            int idx = tid + 256 * k;
            float v = pwg[idx];
            pw2[idx] = make_float2(v, v);
        }
        for (int idx = tid; idx < 576; idx += 256) dws[idx] = gDw[b * 576 + idx];
        if (tid < 64) dbs[tid] = gDb[b * 64 + tid];
    }
    __syncthreads();

    // ---- depthwise 3x3 (pad=1) straight from global; warp w: channels [8w,8w+8) ----
    const float4* xb = (const float4*)(x + (size_t)b * 64 * 16384);
    const float4 z4 = make_float4(0.f, 0.f, 0.f, 0.f);
    bool hasT = (h >= 1), hasB = (h <= 126);

#pragma unroll
    for (int ci = 0; ci < 8; ci++) {
        int c = wid * 8 + ci;
        const float4* plane = xb + (size_t)c * 4096;   // c*128*128/4
        float4 r0 = hasT ? plane[(h - 1) * 32 + lane] : z4;
        float4 r1 =        plane[h       * 32 + lane];
        float4 r2 = hasB ? plane[(h + 1) * 32 + lane] : z4;

        const float* wp = dws + c * 9;
        float a0 = 0.f, a1 = 0.f, a2 = 0.f, a3 = 0.f;
#pragma unroll
        for (int r = 0; r < 3; r++) {
            float4 m = (r == 0) ? r0 : (r == 1) ? r1 : r2;
            float lf = __shfl_up_sync(0xffffffffu, m.w, 1);
            float rg = __shfl_down_sync(0xffffffffu, m.x, 1);
            if (lane == 0)  lf = 0.f;
            if (lane == 31) rg = 0.f;
            float w0 = wp[r * 3 + 0], w1 = wp[r * 3 + 1], w2 = wp[r * 3 + 2];
            a0 += w0 * lf  + w1 * m.x + w2 * m.y;
            a1 += w0 * m.x + w1 * m.y + w2 * m.z;
            a2 += w0 * m.y + w1 * m.z + w2 * m.w;
            a3 += w0 * m.z + w1 * m.w + w2 * rg;
        }
        *(float4*)(ys + c * 128 + 4 * lane) = make_float4(a0, a1, a2, a3);
    }
    __syncthreads();

    // ---- pointwise 64x64 with packed f32x2 FMA; warp w: out-ch [8w,8w+8) ----
    const unsigned long long* ys64 = (const unsigned long long*)ys;
    const unsigned long long* pw64 = (const unsigned long long*)pw2;
    unsigned long long acc[16];
#pragma unroll
    for (int i = 0; i < 16; i++) acc[i] = 0ull;
    int ob = wid * 8;

#pragma unroll 2
    for (int c = 0; c < 64; c++) {
        unsigned long long y0 = ys64[c * 64 + lane];        // w = 2l, 2l+1
        unsigned long long y1 = ys64[c * 64 + 32 + lane];   // w = 64+2l, 64+2l+1
#pragma unroll
        for (int oi = 0; oi < 8; oi++) {
            unsigned long long p = pw64[(ob + oi) * 64 + c];
            asm("fma.rn.f32x2 %0, %1, %2, %0;" : "+l"(acc[2 * oi])     : "l"(y0), "l"(p));
            asm("fma.rn.f32x2 %0, %1, %2, %0;" : "+l"(acc[2 * oi + 1]) : "l"(y1), "l"(p));
        }
    }

    // ---- epilogue: +dbias, store, BN partial stats ----
    float* outb = out + (size_t)(b * 64) * 16384 + (size_t)h * 128;
#pragma unroll
    for (int oi = 0; oi < 8; oi++) {
        int o = ob + oi;
        float db = dbs[o];
        float a0x, a0y, a1x, a1y;
        asm("mov.b64 {%0,%1}, %2;" : "=f"(a0x), "=f"(a0y) : "l"(acc[2 * oi]));
        asm("mov.b64 {%0,%1}, %2;" : "=f"(a1x), "=f"(a1y) : "l"(acc[2 * oi + 1]));
        a0x += db; a0y += db; a1x += db; a1y += db;

        float* orow = outb + (size_t)o * 16384;
        *(float2*)(orow + 2 * lane)      = make_float2(a0x, a0y);
        *(float2*)(orow + 64 + 2 * lane) = make_float2(a1x, a1y);

        float s  = (a0x + a0y) + (a1x + a1y);
        float s2 = a0x * a0x + a0y * a0y + a1x * a1x + a1y * a1y;
#pragma unroll
        for (int off = 16; off; off >>= 1) {
            s  += __shfl_down_sync(0xffffffffu, s,  off);
            s2 += __shfl_down_sync(0xffffffffu, s2, off);
        }
        if (lane == 0) {
            atomicAdd(&gSum[o],   (double)s);
            atomicAdd(&gSumSq[o], (double)s2);
        }
    }
}

// =================================================================================
// Kernel 4: finalize BN scale/shift
// =================================================================================
__global__ void k_finalize(const float* __restrict__ gamma,
                           const float* __restrict__ beta)
{
    int t = threadIdx.x;
    if (t < 64) {
        const double n = 524288.0;   // 32 * 128 * 128
        double mean = gSum[t] / n;
        double var  = gSumSq[t] / n - mean * mean;
        double inv  = 1.0 / sqrt(var + 1e-5);
        double g    = (double)gamma[t];
        gScale[t] = (float)(g * inv);
        gShift[t] = (float)((double)beta[t] - mean * g * inv);
    }
}

// =================================================================================
// Kernel 5: apply BN in place (streaming, float4)
// =================================================================================
__global__ void __launch_bounds__(256) k_bn(float* __restrict__ out) {
    int i = blockIdx.x * 256 + threadIdx.x;      // float4 index
    float4 v = ((const float4*)out)[i];
    int o = (i >> 12) & 63;                      // 4096 float4 per (b,o) plane
    float sc = gScale[o], sh = gShift[o];
    v.x = fmaf(v.x, sc, sh);
    v.y = fmaf(v.y, sc, sh);
    v.z = fmaf(v.z, sc, sh);
    v.w = fmaf(v.w, sc, sh);
    ((float4*)out)[i] = v;
}

// =================================================================================
extern "C" void kernel_launch(void* const* d_in, const int* in_sizes, int n_in,
                              void* d_out, int out_size)
{
    const float* x      = (const float*)d_in[0];
    const float* cg_w1  = (const float*)d_in[1];
    const float* cg_b1  = (const float*)d_in[2];
    const float* cg_w2  = (const float*)d_in[3];
    const float* cg_b2  = (const float*)d_in[4];
    const float* wg_w   = (const float*)d_in[5];
    const float* wg_b   = (const float*)d_in[6];
    const float* pg_w   = (const float*)d_in[7];
    const float* pg_b   = (const float*)d_in[8];
    const float* bg_w   = (const float*)d_in[9];
    const float* bg_b   = (const float*)d_in[10];
    const float* bn_g   = (const float*)d_in[11];
    const float* bn_b   = (const float*)d_in[12];
    float* out = (float*)d_out;

    cudaFuncSetAttribute(k_main, cudaFuncAttributeMaxDynamicSharedMemorySize, 68096);

    k_zero<<<1, 64>>>();
    k_cond_sums<<<2048, 256>>>(x);
    k_gen<<<32, 256>>>(cg_w1, cg_b1, cg_w2, cg_b2, wg_w, wg_b, pg_w, pg_b, bg_w, bg_b);
    dim3 g3(128, 32);
    k_main<<<g3, 256, 68096>>>(x, out);
    k_finalize<<<1, 64>>>(bn_g, bn_b);
    k_bn<<<32768, 256>>>(out);
}

// round 3
// speedup vs baseline: 1.5192x; 1.1279x over previous
#include <cuda_runtime.h>

typedef unsigned long long ull;

// ---------------- device scratch (no runtime allocation allowed) ----------------
__device__ float  gS[32 * 64 * 9];     // strided sums for cond conv
__device__ float  gDw[32 * 576];       // per-sample depthwise weights
__device__ float  gPw[32 * 4096];      // per-sample pointwise weights [b][o][c]
__device__ float  gDb[32 * 64];        // per-sample dynamic bias
__device__ double gSum[64], gSumSq[64];// BN statistics accumulators
__device__ float  gScale[64], gShift[64];

// =================================================================================
// Kernel 0: zero stats (graph replays must be deterministic)
// =================================================================================
__global__ void k_zero() {
    int t = threadIdx.x;
    if (t < 64) { gSum[t] = 0.0; gSumSq[t] = 0.0; }
}

// =================================================================================
// Kernel 1: per-(b,c) 9 strided sums S[kh][kw] = sum_{oh,ow} x[2oh+kh, 2ow+kw]
// =================================================================================
__global__ void __launch_bounds__(256) k_cond_sums(const float* __restrict__ x) {
    int bc = blockIdx.x;                 // b*64 + c
    int t  = threadIdx.x;
    const float* base = x + (size_t)bc * 16384;

    int i  = t >> 1;                     // row 0..127
    int j0 = (t & 1) * 64;               // half-row
    const float4* row4 = (const float4*)(base + i * 128 + j0);

    float ca0 = 0.f, ca1 = 0.f, ca2 = 0.f;
#pragma unroll
    for (int k = 0; k < 16; k++) {
        float4 v = row4[k];
        int j = j0 + 4 * k;
        ca0 += v.x + ((j <= 122) ? v.z : 0.f);
        ca1 += v.y + ((j <= 122) ? v.w : 0.f);
        ca2 += ((j >= 2) ? v.x : 0.f) + v.z;
    }
    bool ev = ((i & 1) == 0);
    float f0 = (ev  && i <= 124) ? 1.f : 0.f;
    float f1 = (!ev && i <= 125) ? 1.f : 0.f;
    float f2 = (ev  && i >= 2)   ? 1.f : 0.f;

    float bins[9] = { f0*ca0, f0*ca1, f0*ca2,
                      f1*ca0, f1*ca1, f1*ca2,
                      f2*ca0, f2*ca1, f2*ca2 };
#pragma unroll
    for (int off = 16; off; off >>= 1)
#pragma unroll
        for (int k = 0; k < 9; k++)
            bins[k] += __shfl_down_sync(0xffffffffu, bins[k], off);

    __shared__ float red[8][9];
    int lane = t & 31, w = t >> 5;
    if (lane == 0)
#pragma unroll
        for (int k = 0; k < 9; k++) red[w][k] = bins[k];
    __syncthreads();
    if (t < 9) {
        float s = 0.f;
#pragma unroll
        for (int ww = 0; ww < 8; ww++) s += red[ww][t];
        gS[bc * 9 + t] = s;
    }
}

// =================================================================================
// Kernel 2: per-sample condition vector + dynamic weight generation (tiny GEMMs)
// =================================================================================
__global__ void __launch_bounds__(256) k_gen(
    const float* __restrict__ cg_w1, const float* __restrict__ cg_b1,
    const float* __restrict__ cg_w2, const float* __restrict__ cg_b2,
    const float* __restrict__ wg_w,  const float* __restrict__ wg_b,
    const float* __restrict__ pg_w,  const float* __restrict__ pg_b,
    const float* __restrict__ bg_w,  const float* __restrict__ bg_b)
{
    __shared__ float Ss[576];
    __shared__ float parts[256];
    __shared__ float c0[16];
    __shared__ float cond[16];

    int b = blockIdx.x;
    int t = threadIdx.x;

    for (int idx = t; idx < 576; idx += 256) Ss[idx] = gS[b * 576 + idx];
    __syncthreads();

    {
        int co = t >> 4, part = t & 15;
        const float* wrow = cg_w1 + co * 576 + part * 36;
        const float* srow = Ss + part * 36;
        float s = 0.f;
#pragma unroll
        for (int k = 0; k < 36; k++) s += wrow[k] * srow[k];
        parts[t] = s;
    }
    __syncthreads();
    if (t < 16) {
        float s = 0.f;
#pragma unroll
        for (int p = 0; p < 16; p++) s += parts[t * 16 + p];
        s = s * (1.0f / 3969.0f) + cg_b1[t];
        c0[t] = fmaxf(s, 0.f);
    }
    __syncthreads();
    if (t < 16) {
        float s = cg_b2[t];
#pragma unroll
        for (int i = 0; i < 16; i++) s += c0[i] * cg_w2[t * 16 + i];
        cond[t] = fmaxf(s, 0.f);
    }
    __syncthreads();

    for (int r = t; r < 576; r += 256) {
        float s = wg_b[r];
        const float* wr = wg_w + r * 16;
#pragma unroll
        for (int q = 0; q < 16; q++) s += cond[q] * wr[q];
        gDw[b * 576 + r] = fmaxf(s, 0.f);
    }
    for (int r = t; r < 4096; r += 256) {
        float s = pg_b[r];
        const float* wr = pg_w + r * 16;
#pragma unroll
        for (int q = 0; q < 16; q++) s += cond[q] * wr[q];
        gPw[b * 4096 + r] = fmaxf(s, 0.f);
    }
    if (t < 64) {
        float s = bg_b[t];
        const float* wr = bg_w + t * 16;
#pragma unroll
        for (int q = 0; q < 16; q++) s += cond[q] * wr[q];
        gDb[b * 64 + t] = s;
    }
}

// =================================================================================
// Kernel 3: fused depthwise3x3 (global->regs, shuffle halo) + pointwise(64x64)
//   c-pair-split f32x2 pointwise; one block per (h, b); 256 threads; 4 CTAs/SM.
// smem (floats):
//   ys2 [32 c2][128 w] float2-interleaved  offset 0      (8192)
//   pw  [64 o][64 c]                        offset 8192   (4096)
//   dws [576]                               offset 12288
//   dbs [64]                                offset 12864
//   sst [128]  (s[64], s2[64])              offset 12928  -> 13056 fl = 52224 B
// =================================================================================
__global__ void __launch_bounds__(256, 4) k_main(const float* __restrict__ x,
                                                 float* __restrict__ out)
{
    extern __shared__ float sm[];
    float* ys2 = sm;
    float* pw  = sm + 8192;
    float* dws = sm + 12288;
    float* dbs = sm + 12864;
    float* sst = sm + 12928;

    int tid  = threadIdx.x;
    int lane = tid & 31, wid = tid >> 5;
    int h = blockIdx.x, b = blockIdx.y;

    // ---- stage per-sample dynamic weights into smem ----
    {
        const float4* pwg = (const float4*)(gPw + b * 4096);
        float4* pw4 = (float4*)pw;
#pragma unroll
        for (int k = 0; k < 4; k++) pw4[tid + 256 * k] = pwg[tid + 256 * k];
        for (int idx = tid; idx < 576; idx += 256) dws[idx] = gDw[b * 576 + idx];
        if (tid < 64) dbs[tid] = gDb[b * 64 + tid];
        if (tid < 128) sst[tid] = 0.f;
    }
    __syncthreads();

    // ---- depthwise 3x3 (pad=1) straight from global; warp w: channels [8w,8w+8) ----
    const float4* xb = (const float4*)(x + (size_t)b * 64 * 16384);
    const float4 z4 = make_float4(0.f, 0.f, 0.f, 0.f);
    bool hasT = (h >= 1), hasB = (h <= 126);

#pragma unroll
    for (int pr = 0; pr < 4; pr++) {           // channel pairs (2c2, 2c2+1)
        float acc_e[4], acc_o[4];
#pragma unroll
        for (int half = 0; half < 2; half++) {
            int c = wid * 8 + pr * 2 + half;
            const float4* plane = xb + (size_t)c * 4096;
            float4 r0 = hasT ? plane[(h - 1) * 32 + lane] : z4;
            float4 r1 =        plane[h       * 32 + lane];
            float4 r2 = hasB ? plane[(h + 1) * 32 + lane] : z4;

            const float* wp = dws + c * 9;
            float a0 = 0.f, a1 = 0.f, a2 = 0.f, a3 = 0.f;
#pragma unroll
            for (int r = 0; r < 3; r++) {
                float4 m = (r == 0) ? r0 : (r == 1) ? r1 : r2;
                float lf = __shfl_up_sync(0xffffffffu, m.w, 1);
                float rg = __shfl_down_sync(0xffffffffu, m.x, 1);
                if (lane == 0)  lf = 0.f;
                if (lane == 31) rg = 0.f;
                float w0 = wp[r * 3 + 0], w1 = wp[r * 3 + 1], w2 = wp[r * 3 + 2];
                a0 += w0 * lf  + w1 * m.x + w2 * m.y;
                a1 += w0 * m.x + w1 * m.y + w2 * m.z;
                a2 += w0 * m.y + w1 * m.z + w2 * m.w;
                a3 += w0 * m.z + w1 * m.w + w2 * rg;
            }
            float* dst = half ? acc_o : acc_e;
            dst[0] = a0; dst[1] = a1; dst[2] = a2; dst[3] = a3;
        }
        // interleaved store: ys2[c2][w] float2 = (y_even[w], y_odd[w]); w = 4*lane..
        int c2 = wid * 4 + pr;
        float4* dst4 = (float4*)ys2 + c2 * 64 + 2 * lane;
        dst4[0] = make_float4(acc_e[0], acc_o[0], acc_e[1], acc_o[1]);
        dst4[1] = make_float4(acc_e[2], acc_o[2], acc_e[3], acc_o[3]);
    }
    __syncthreads();

    // ---- pointwise: c-pair split-K in f32x2; warp handles o [8w,8w+8), two w-halves ----
    const ull* pw64 = (const ull*)pw;            // pw64[o*32 + c2] = (pw[o][2c2], pw[o][2c2+1])
    int ob = wid * 8;
    float* outb = out + (size_t)(b * 64) * 16384 + (size_t)h * 128;

#pragma unroll 1
    for (int q = 0; q < 2; q++) {                // w-half: w = 64q + {2*lane, 2*lane+1}
        ull acc[16];
#pragma unroll
        for (int i = 0; i < 16; i++) acc[i] = 0ull;

        const ulonglong2* ybase = (const ulonglong2*)ys2 + 32 * q + lane;

#pragma unroll 8
        for (int c2 = 0; c2 < 32; c2++) {
            ulonglong2 yv = ybase[c2 * 64];      // (y2[c2][w0], y2[c2][w0+1])
            ull y0 = yv.x, y1 = yv.y;
#pragma unroll
            for (int g = 0; g < 2; g++) {        // two groups of 4 o (limits live p regs)
                ull p0 = pw64[(ob + 4 * g + 0) * 32 + c2];
                ull p1 = pw64[(ob + 4 * g + 1) * 32 + c2];
                ull p2 = pw64[(ob + 4 * g + 2) * 32 + c2];
                ull p3 = pw64[(ob + 4 * g + 3) * 32 + c2];
                asm("fma.rn.f32x2 %0, %1, %2, %0;" : "+l"(acc[8*g+0]) : "l"(y0), "l"(p0));
                asm("fma.rn.f32x2 %0, %1, %2, %0;" : "+l"(acc[8*g+1]) : "l"(y1), "l"(p0));
                asm("fma.rn.f32x2 %0, %1, %2, %0;" : "+l"(acc[8*g+2]) : "l"(y0), "l"(p1));
                asm("fma.rn.f32x2 %0, %1, %2, %0;" : "+l"(acc[8*g+3]) : "l"(y1), "l"(p1));
                asm("fma.rn.f32x2 %0, %1, %2, %0;" : "+l"(acc[8*g+4]) : "l"(y0), "l"(p2));
                asm("fma.rn.f32x2 %0, %1, %2, %0;" : "+l"(acc[8*g+5]) : "l"(y1), "l"(p2));
                asm("fma.rn.f32x2 %0, %1, %2, %0;" : "+l"(acc[8*g+6]) : "l"(y0), "l"(p3));
                asm("fma.rn.f32x2 %0, %1, %2, %0;" : "+l"(acc[8*g+7]) : "l"(y1), "l"(p3));
            }
        }

        // epilogue for this w-half: value = acc.x + acc.y + dbias
#pragma unroll
        for (int oi = 0; oi < 8; oi++) {
            int o = ob + oi;
            float db = dbs[o];
            float a0x, a0y, a1x, a1y;
            asm("mov.b64 {%0,%1}, %2;" : "=f"(a0x), "=f"(a0y) : "l"(acc[2*oi]));
            asm("mov.b64 {%0,%1}, %2;" : "=f"(a1x), "=f"(a1y) : "l"(acc[2*oi+1]));
            float v0 = a0x + a0y + db;
            float v1 = a1x + a1y + db;

            *(float2*)(outb + (size_t)o * 16384 + 64 * q + 2 * lane) = make_float2(v0, v1);

            float s  = v0 + v1;
            float s2 = v0 * v0 + v1 * v1;
#pragma unroll
            for (int off = 16; off; off >>= 1) {
                s  += __shfl_down_sync(0xffffffffu, s,  off);
                s2 += __shfl_down_sync(0xffffffffu, s2, off);
            }
            if (lane == 0) {
                atomicAdd(&sst[o],      s);
                atomicAdd(&sst[64 + o], s2);
            }
        }
    }

    __syncthreads();
    if (tid < 64)                 atomicAdd(&gSum[tid],         (double)sst[tid]);
    else if (tid < 128)           atomicAdd(&gSumSq[tid - 64],  (double)sst[tid]);
}

// =================================================================================
// Kernel 4: finalize BN scale/shift
// =================================================================================
__global__ void k_finalize(const float* __restrict__ gamma,
                           const float* __restrict__ beta)
{
    int t = threadIdx.x;
    if (t < 64) {
        const double n = 524288.0;   // 32 * 128 * 128
        double mean = gSum[t] / n;
        double var  = gSumSq[t] / n - mean * mean;
        double inv  = 1.0 / sqrt(var + 1e-5);
        double g    = (double)gamma[t];
        gScale[t] = (float)(g * inv);
        gShift[t] = (float)((double)beta[t] - mean * g * inv);
    }
}

// =================================================================================
// Kernel 5: apply BN in place (streaming, float4)
// =================================================================================
__global__ void __launch_bounds__(256) k_bn(float* __restrict__ out) {
    int i = blockIdx.x * 256 + threadIdx.x;      // float4 index
    float4 v = ((const float4*)out)[i];
    int o = (i >> 12) & 63;                      // 4096 float4 per (b,o) plane
    float sc = gScale[o], sh = gShift[o];
    v.x = fmaf(v.x, sc, sh);
    v.y = fmaf(v.y, sc, sh);
    v.z = fmaf(v.z, sc, sh);
    v.w = fmaf(v.w, sc, sh);
    ((float4*)out)[i] = v;
}

// =================================================================================
extern "C" void kernel_launch(void* const* d_in, const int* in_sizes, int n_in,
                              void* d_out, int out_size)
{
    const float* x      = (const float*)d_in[0];
    const float* cg_w1  = (const float*)d_in[1];
    const float* cg_b1  = (const float*)d_in[2];
    const float* cg_w2  = (const float*)d_in[3];
    const float* cg_b2  = (const float*)d_in[4];
    const float* wg_w   = (const float*)d_in[5];
    const float* wg_b   = (const float*)d_in[6];
    const float* pg_w   = (const float*)d_in[7];
    const float* pg_b   = (const float*)d_in[8];
    const float* bg_w   = (const float*)d_in[9];
    const float* bg_b   = (const float*)d_in[10];
    const float* bn_g   = (const float*)d_in[11];
    const float* bn_b   = (const float*)d_in[12];
    float* out = (float*)d_out;

    cudaFuncSetAttribute(k_main, cudaFuncAttributeMaxDynamicSharedMemorySize, 52224);

    k_zero<<<1, 64>>>();
    k_cond_sums<<<2048, 256>>>(x);
    k_gen<<<32, 256>>>(cg_w1, cg_b1, cg_w2, cg_b2, wg_w, wg_b, pg_w, pg_b, bg_w, bg_b);
    dim3 g3(128, 32);
    k_main<<<g3, 256, 52224>>>(x, out);
    k_finalize<<<1, 64>>>(bn_g, bn_b);
    k_bn<<<32768, 256>>>(out);
}